// round 14
// baseline (speedup 1.0000x reference)
#include <cuda_runtime.h>
#include <cuda_bf16.h>
#include <cuda_fp16.h>
#include <cstdint>

// Problem dims
#define BB  256
#define TT  256
#define IND 128
#define SS  1024

// ---------------- scratch (__device__ globals) ------------------------------
__device__ float g_ext[(size_t)TT * BB * SS];            // [t][b][s] fp32
__device__ __half g_sA[BB * SS];                         // state fp16 (ping)
__device__ __half g_sB[BB * SS];                         // state fp16 (pong)
__device__ __half g_W1[SS * SS], g_W2[SS * SS];          // weights fp16
__device__ __nv_bfloat16 g_xh[(size_t)BB * TT * IND], g_xl[(size_t)BB * TT * IND];
__device__ __nv_bfloat16 g_Winh[SS * IND], g_Winl[SS * IND];

// ---------------- helpers ---------------------------------------------------
__device__ __forceinline__ uint32_t smem_u32(const void* p) {
    uint32_t a;
    asm("{ .reg .u64 t; cvta.to.shared.u64 t, %1; cvt.u32.u64 %0, t; }" : "=r"(a) : "l"(p));
    return a;
}
__device__ __forceinline__ void cp16(uint32_t dst, const void* src) {
    asm volatile("cp.async.cg.shared.global [%0], [%1], 16;" :: "r"(dst), "l"(src));
}
__device__ __forceinline__ void cp_commit() { asm volatile("cp.async.commit_group;"); }
__device__ __forceinline__ void cp_wait0()  { asm volatile("cp.async.wait_group 0;"); }
__device__ __forceinline__ void cp_wait1()  { asm volatile("cp.async.wait_group 1;"); }
__device__ __forceinline__ void gdc_wait()   { asm volatile("griddepcontrol.wait;" ::: "memory"); }
__device__ __forceinline__ void gdc_launch() { asm volatile("griddepcontrol.launch_dependents;"); }
__device__ __forceinline__ void bar_named(int id) {
    asm volatile("bar.sync %0, 128;" :: "r"(id) : "memory");
}

__device__ __forceinline__ void mma_bf16(float* c, const uint32_t* a,
                                         uint32_t b0, uint32_t b1) {
    asm volatile(
        "mma.sync.aligned.m16n8k16.row.col.f32.bf16.bf16.f32 "
        "{%0,%1,%2,%3}, {%4,%5,%6,%7}, {%8,%9}, {%0,%1,%2,%3};"
        : "+f"(c[0]), "+f"(c[1]), "+f"(c[2]), "+f"(c[3])
        : "r"(a[0]), "r"(a[1]), "r"(a[2]), "r"(a[3]), "r"(b0), "r"(b1));
}
__device__ __forceinline__ void mma_f16(float* c, const uint32_t* a,
                                        uint32_t b0, uint32_t b1) {
    asm volatile(
        "mma.sync.aligned.m16n8k16.row.col.f32.f16.f16.f32 "
        "{%0,%1,%2,%3}, {%4,%5,%6,%7}, {%8,%9}, {%0,%1,%2,%3};"
        : "+f"(c[0]), "+f"(c[1]), "+f"(c[2]), "+f"(c[3])
        : "r"(a[0]), "r"(a[1]), "r"(a[2]), "r"(a[3]), "r"(b0), "r"(b1));
}
__device__ __forceinline__ void ldsm_x4(uint32_t* r, uint32_t addr) {
    asm volatile("ldmatrix.sync.aligned.m8n8.x4.shared.b16 {%0,%1,%2,%3}, [%4];"
                 : "=r"(r[0]), "=r"(r[1]), "=r"(r[2]), "=r"(r[3]) : "r"(addr));
}

// ---------------- layer GEMM (fp16, CTA 64x64, warp 32x32, PDL) -------------
// O = relu(A @ W^T + bias) (+ ext_next). Grid (4, 16) = 64 CTAs.
// 16 warps = 4 K-groups x (wm2 x wn2); group q owns k in [q*256, q*256+256),
// 8 chunks of 32 through a private 2-stage pipeline (named-bar group sync).
// 80-byte padded SMEM rows: stride 80 mod 128 covers all 8 16B banks ->
// conflict-free ldmatrix without XOR swizzle.
// SMEM 96KB -> 2 CTAs/SM: next layer pre-places + prefetches W under PDL.
#define M_TILE 64
#define N_TILE 64
#define KQ     256                // k-range per group
#define KCH    32                 // chunk width
#define NCH    8                  // chunks per group
#define ROWB   80                 // padded row stride (bytes) for 64B data
#define STG_B  5120               // B offset inside a stage (A is 64*80)
#define STGSZ  10240              // stage: A 5120 + B 5120
#define GREG   (2 * STGSZ)        // per-group region = 20480
#define EXT_OFF (4 * GREG)        // 81920
#define SM_TOTAL (EXT_OFF + 16384) // 98304 -> 2 CTAs/SM
#define NTHR   512

// load a 64-row x 32-col fp16 slab into padded-row stage (128 threads)
__device__ __forceinline__ void load_T(uint32_t dst, int k0, int gtid, int r0,
    const __half* __restrict__ P)
{
    #pragma unroll
    for (int i = 0; i < 2; i++) {
        int u = gtid + (i << 7);         // 0..255 = 64 rows x 4 units
        int row = u >> 2, cu = u & 3;
        cp16(dst + row * ROWB + cu * 16,
             P + (size_t)(r0 + row) * SS + k0 + cu * 8);
    }
}

__global__ __launch_bounds__(NTHR, 2) void layer_kernel(
    const __half* __restrict__ A, const __half* __restrict__ W,
    const float* __restrict__ bias, const float* __restrict__ ext_next,
    __half* __restrict__ O)
{
    extern __shared__ char smem[];
    const uint32_t sb = smem_u32(smem);
    const int tid = threadIdx.x;
    const int wid = tid >> 5, lane = tid & 31;
    const int gl = lane >> 2, t4 = lane & 3;
    const int q  = wid >> 2;             // K group 0..3
    const int wm = (wid >> 1) & 1;       // rows wm*32
    const int wn = wid & 1;              // cols wn*32
    const int gtid = tid & 127;
    const int m0 = blockIdx.x * M_TILE, n0 = blockIdx.y * N_TILE;
    const int kbase = q * KQ;
    const uint32_t gb = sb + q * GREG;

    const int fr = lane & 15;            // ldsm fragment row
    const int khalf = (lane >> 4) & 1;   // ldsm k-half (16B)

    // ---- prologue: weight + ext prefetch BEFORE the grid dependency ----
    load_T(gb + STG_B, kbase, gtid, n0, W);
    if (ext_next) {                       // ext tile 64x64 fp32 = 16KB
        #pragma unroll
        for (int i = 0; i < 2; i++) {
            int u = tid + (i << 9);       // 0..1023 = 64 rows x 16 units
            int row = u >> 4, cu = u & 15;
            cp16(sb + EXT_OFF + row * 256 + cu * 16,
                 ext_next + (size_t)(m0 + row) * SS + n0 + cu * 4);
        }
    }
    cp_commit();                                            // g0 = B0 (+ext)
    load_T(gb + STGSZ + STG_B, kbase + KCH, gtid, n0, W);
    cp_commit();                                            // g1 = B1
    gdc_wait();                                             // prev layer done
    load_T(gb, kbase, gtid, m0, A);              cp_commit(); // g2 = A0
    load_T(gb + STGSZ, kbase + KCH, gtid, m0, A); cp_commit(); // g3 = A1

    float acc[2][4][4] = {};              // [mf][nf][reg]

    // ---- group-private mainloop: 8 chunks, 2 stages, named-bar sync ----
    #pragma unroll 1
    for (int c = 0; c < NCH; c++) {
        if (c == NCH - 1) cp_wait0(); else cp_wait1();
        bar_named(q + 1);                 // chunk-c data complete, group-wide
        const uint32_t aB = gb + (c & 1) * STGSZ;
        const uint32_t bB = aB + STG_B;
        #pragma unroll
        for (int j = 0; j < 2; j++) {     // 2 k16 per chunk
            const uint32_t koff = j * 32 + khalf * 16;
            uint32_t a0[4], a1[4];
            ldsm_x4(a0, aB + (wm * 32 + fr) * ROWB + koff);
            ldsm_x4(a1, aB + (wm * 32 + 16 + fr) * ROWB + koff);
            #pragma unroll
            for (int bf = 0; bf < 2; bf++) {
                uint32_t b[4];
                ldsm_x4(b, bB + (wn * 32 + bf * 16 + fr) * ROWB + koff);
                mma_f16(acc[0][bf * 2 + 0], a0, b[0], b[2]);
                mma_f16(acc[0][bf * 2 + 1], a0, b[1], b[3]);
                mma_f16(acc[1][bf * 2 + 0], a1, b[0], b[2]);
                mma_f16(acc[1][bf * 2 + 1], a1, b[1], b[3]);
            }
        }
        if (c + 2 < NCH) {
            bar_named(q + 1);             // all group warps done with chunk c
            const uint32_t sp = gb + (c & 1) * STGSZ;  // stage just freed
            load_T(sp, kbase + (c + 2) * KCH, gtid, m0, A);
            load_T(sp + STG_B, kbase + (c + 2) * KCH, gtid, n0, W);
            cp_commit();
        }
    }
    __syncthreads();                      // all groups done -> overlay stages

    // ---- symmetric 4-way reduction: warp q keeps nf=q, exchanges rest ----
    const int tile = wm * 2 + wn;         // 0..3
    float4* scr = (float4*)smem;          // 64KB scratch over stage region
    #pragma unroll
    for (int mf = 0; mf < 2; mf++)
        #pragma unroll
        for (int nf = 0; nf < 4; nf++)
            if (nf != q)
                scr[(((tile * 4 + nf) * 4 + q) * 2 + mf) * 32 + lane] =
                    make_float4(acc[mf][nf][0], acc[mf][nf][1],
                                acc[mf][nf][2], acc[mf][nf][3]);
    __syncthreads();
    float r[2][4];
    #pragma unroll
    for (int mf = 0; mf < 2; mf++) {
        r[mf][0] = acc[mf][q][0]; r[mf][1] = acc[mf][q][1];
        r[mf][2] = acc[mf][q][2]; r[mf][3] = acc[mf][q][3];
    }
    #pragma unroll
    for (int p = 0; p < 4; p++) {
        if (p != q) {
            #pragma unroll
            for (int mf = 0; mf < 2; mf++) {
                float4 v = scr[(((tile * 4 + q) * 4 + p) * 2 + mf) * 32 + lane];
                r[mf][0] += v.x; r[mf][1] += v.y; r[mf][2] += v.z; r[mf][3] += v.w;
            }
        }
    }

    // ---- epilogue: every warp stores its nf=q quadrant (2 m-frags) ----
    const int col = n0 + wn * 32 + q * 8 + t4 * 2;
    float2 bb = *(const float2*)(bias + col);
    #pragma unroll
    for (int mf = 0; mf < 2; mf++) {
        const int row0 = m0 + wm * 32 + mf * 16 + gl;
        const int row1 = row0 + 8;
        float v00 = fmaxf(r[mf][0] + bb.x, 0.0f);
        float v01 = fmaxf(r[mf][1] + bb.y, 0.0f);
        float v10 = fmaxf(r[mf][2] + bb.x, 0.0f);
        float v11 = fmaxf(r[mf][3] + bb.y, 0.0f);
        if (ext_next) {
            const char* eb = smem + EXT_OFF;
            const int ecol = (wn * 32 + q * 8 + t4 * 2) * 4;
            float2 e0 = *(const float2*)(eb + (wm * 32 + mf * 16 + gl) * 256 + ecol);
            float2 e1 = *(const float2*)(eb + (wm * 32 + mf * 16 + gl + 8) * 256 + ecol);
            v00 += e0.x; v01 += e0.y; v10 += e1.x; v11 += e1.y;
        }
        *(uint32_t*)(O + (size_t)row0 * SS + col) =
            (uint32_t)__half_as_ushort(__float2half_rn(v00))
            | ((uint32_t)__half_as_ushort(__float2half_rn(v01)) << 16);
        *(uint32_t*)(O + (size_t)row1 * SS + col) =
            (uint32_t)__half_as_ushort(__float2half_rn(v10))
            | ((uint32_t)__half_as_ushort(__float2half_rn(v11)) << 16);
    }
    gdc_launch();                         // after stores: safe ordering
}

// ---------------- input projection (bf16 3-term MMA; also writes s0) --------
#define PA_HI 0
#define PA_LO 16384
#define PB_HI 32768
#define PB_LO 49152
#define P_SM  65536

#define SWU16(cu, row) ((((cu) & 8) | (((cu) & 7) ^ ((row) & 7))) << 4)

__global__ __launch_bounds__(256) void proj_mma(
    const __nv_bfloat16* __restrict__ Xh, const __nv_bfloat16* __restrict__ Xl,
    const __nv_bfloat16* __restrict__ Wh, const __nv_bfloat16* __restrict__ Wl,
    const float* __restrict__ bias, float* __restrict__ Out,
    __half* __restrict__ S0)
{
    extern __shared__ char smem[];
    const uint32_t sb = smem_u32(smem);
    const int tid = threadIdx.x;
    const int wid = tid >> 5, lane = tid & 31;
    const int g = lane >> 2, t4 = lane & 3;
    const int wm = (wid >> 1) << 4;
    const int wn = (wid & 1) << 5;
    const int m0 = blockIdx.x * 64, n0 = blockIdx.y * 64;

    #pragma unroll
    for (int i = 0; i < 16; i++) {
        int u = tid + (i << 8);
        const __nv_bfloat16* src;
        uint32_t dst;
        if (u < 2048) {
            int sel = u >> 10, v = u & 1023;
            int row = v >> 4, cu = v & 15;
            src = (sel ? Xl : Xh) + (size_t)(m0 + row) * IND + cu * 8;
            dst = sb + (sel ? PA_LO : PA_HI) + row * 256 + SWU16(cu, row);
        } else {
            int w = u - 2048;
            int sel = w >> 10, v = w & 1023;
            int row = v >> 4, cu = v & 15;
            src = (sel ? Wl : Wh) + (size_t)(n0 + row) * IND + cu * 8;
            dst = sb + (sel ? PB_LO : PB_HI) + row * 256 + SWU16(cu, row);
        }
        cp16(dst, src);
    }
    cp_commit();
    cp_wait0();
    __syncthreads();

    const int lr = lane & 7;
    const int half8 = (lane >> 3) & 1;
    const int khalf = (lane >> 4) & 1;
    const int rowA = wm + half8 * 8 + lr;
    const int rowB = wn + half8 * 8 + lr;

    float acc[4][4] = {};
    #pragma unroll
    for (int ks = 0; ks < 8; ks++) {
        const int u = ks * 2 + khalf;
        uint32_t ah[4], al[4];
        ldsm_x4(ah, sb + PA_HI + rowA * 256 + SWU16(u, rowA));
        ldsm_x4(al, sb + PA_LO + rowA * 256 + SWU16(u, rowA));
        #pragma unroll
        for (int jj = 0; jj < 2; jj++) {
            uint32_t bh[4], bl[4];
            ldsm_x4(bh, sb + PB_HI + (rowB + jj * 16) * 256 + SWU16(u, rowB + jj * 16));
            ldsm_x4(bl, sb + PB_LO + (rowB + jj * 16) * 256 + SWU16(u, rowB + jj * 16));
            mma_bf16(acc[jj * 2],     ah, bh[0], bh[2]);
            mma_bf16(acc[jj * 2],     ah, bl[0], bl[2]);
            mma_bf16(acc[jj * 2],     al, bh[0], bh[2]);
            mma_bf16(acc[jj * 2 + 1], ah, bh[1], bh[3]);
            mma_bf16(acc[jj * 2 + 1], ah, bl[1], bl[3]);
            mma_bf16(acc[jj * 2 + 1], al, bh[1], bh[3]);
        }
    }

    const int r0 = m0 + wm + g;
    const int r1 = r0 + 8;
    const int b0r = r0 >> 8, t0r = r0 & 255;
    const int b1r = r1 >> 8, t1r = r1 & 255;
    #pragma unroll
    for (int j = 0; j < 4; j++) {
        const int col = n0 + wn + j * 8 + t4 * 2;
        float2 bb = *(const float2*)(bias + col);
        float2 o0 = make_float2(acc[j][0] + bb.x, acc[j][1] + bb.y);
        float2 o1 = make_float2(acc[j][2] + bb.x, acc[j][3] + bb.y);
        *(float2*)(Out + ((size_t)t0r * BB + b0r) * SS + col) = o0;
        *(float2*)(Out + ((size_t)t1r * BB + b1r) * SS + col) = o1;
        if (t0r == 0) {
            *(uint32_t*)(S0 + (size_t)b0r * SS + col) =
                (uint32_t)__half_as_ushort(__float2half_rn(o0.x))
                | ((uint32_t)__half_as_ushort(__float2half_rn(o0.y)) << 16);
        }
    }
}

// ---------------- fused prolog: all conversions in ONE launch ----------------
#define N_W   (SS * SS / 4)
#define N_X   ((size_t)BB * TT * IND / 4)
#define N_WIN (SS * IND / 4)
#define N_TOT (2 * N_W + (int)N_X + N_WIN)

__global__ void prep_kernel(
    const float4* __restrict__ Wr1, const float4* __restrict__ Wr2,
    const float4* __restrict__ X,   const float4* __restrict__ Win,
    uint2* __restrict__ W1, uint2* __restrict__ W2,
    uint2* __restrict__ xh, uint2* __restrict__ xl,
    uint2* __restrict__ wih, uint2* __restrict__ wil)
{
    int i = blockIdx.x * blockDim.x + threadIdx.x;
    if (i >= N_TOT) return;
    if (i < 2 * N_W) {
        const float4* src = (i < N_W) ? Wr1 : Wr2;
        uint2* dst        = (i < N_W) ? W1  : W2;
        int k = (i < N_W) ? i : i - N_W;
        float4 v = src[k];
        uint2 O;
        O.x = (uint32_t)__half_as_ushort(__float2half_rn(v.x))
            | ((uint32_t)__half_as_ushort(__float2half_rn(v.y)) << 16);
        O.y = (uint32_t)__half_as_ushort(__float2half_rn(v.z))
            | ((uint32_t)__half_as_ushort(__float2half_rn(v.w)) << 16);
        dst[k] = O;
    } else {
        int k = i - 2 * N_W;
        const float4* src; uint2 *dh, *dl;
        if (k < (int)N_X) { src = X; dh = xh; dl = xl; }
        else { k -= (int)N_X; src = Win; dh = wih; dl = wil; }
        float4 v = src[k];
        __nv_bfloat16 h0 = __float2bfloat16(v.x), h1 = __float2bfloat16(v.y);
        __nv_bfloat16 h2 = __float2bfloat16(v.z), h3 = __float2bfloat16(v.w);
        __nv_bfloat16 l0 = __float2bfloat16(v.x - __bfloat162float(h0));
        __nv_bfloat16 l1 = __float2bfloat16(v.y - __bfloat162float(h1));
        __nv_bfloat16 l2 = __float2bfloat16(v.z - __bfloat162float(h2));
        __nv_bfloat16 l3 = __float2bfloat16(v.w - __bfloat162float(h3));
        uint2 H, L;
        H.x = (uint32_t)__bfloat16_as_ushort(h0) | ((uint32_t)__bfloat16_as_ushort(h1) << 16);
        H.y = (uint32_t)__bfloat16_as_ushort(h2) | ((uint32_t)__bfloat16_as_ushort(h3) << 16);
        L.x = (uint32_t)__bfloat16_as_ushort(l0) | ((uint32_t)__bfloat16_as_ushort(l1) << 16);
        L.y = (uint32_t)__bfloat16_as_ushort(l2) | ((uint32_t)__bfloat16_as_ushort(l3) << 16);
        dh[k] = H; dl[k] = L;
    }
}

// ---------------- broadcast final state (fp16 -> fp32, all timesteps) -------
__global__ void bcastH_kernel(const uint2* __restrict__ s, float4* __restrict__ out)
{
    int i = blockIdx.x * blockDim.x + threadIdx.x;
    int b  = i >> 16;
    int s4 = i & 255;
    uint2 H = s[(b << 8) + s4];
    float4 o;
    o.x = __half2float(__ushort_as_half((unsigned short)(H.x & 0xFFFF)));
    o.y = __half2float(__ushort_as_half((unsigned short)(H.x >> 16)));
    o.z = __half2float(__ushort_as_half((unsigned short)(H.y & 0xFFFF)));
    o.w = __half2float(__ushort_as_half((unsigned short)(H.y >> 16)));
    out[i] = o;
}

// ---------------- driver ----------------------------------------------------
extern "C" void kernel_launch(void* const* d_in, const int* in_sizes, int n_in,
                              void* d_out, int out_size)
{
    const float* x      = (const float*)d_in[0];
    const float* W_in   = (const float*)d_in[1];
    const float* b_in   = (const float*)d_in[2];
    const float* W_rec  = (const float*)d_in[3];
    const float* b_rec  = (const float*)d_in[4];
    const float* W_rec2 = (const float*)d_in[5];
    const float* b_rec2 = (const float*)d_in[6];
    float* out = (float*)d_out;

    float* ext;
    __half *sA, *sB, *W1, *W2;
    __nv_bfloat16 *xh, *xl, *Winh, *Winl;
    cudaGetSymbolAddress((void**)&ext, g_ext);
    cudaGetSymbolAddress((void**)&sA,  g_sA);
    cudaGetSymbolAddress((void**)&sB,  g_sB);
    cudaGetSymbolAddress((void**)&W1,  g_W1);
    cudaGetSymbolAddress((void**)&W2,  g_W2);
    cudaGetSymbolAddress((void**)&xh,  g_xh);
    cudaGetSymbolAddress((void**)&xl,  g_xl);
    cudaGetSymbolAddress((void**)&Winh, g_Winh);
    cudaGetSymbolAddress((void**)&Winl, g_Winl);

    cudaFuncSetAttribute(layer_kernel, cudaFuncAttributeMaxDynamicSharedMemorySize, SM_TOTAL);
    cudaFuncSetAttribute(proj_mma,     cudaFuncAttributeMaxDynamicSharedMemorySize, P_SM);

    // Launch 0: fused prolog
    prep_kernel<<<(N_TOT + 255) / 256, 256>>>(
        (const float4*)W_rec, (const float4*)W_rec2,
        (const float4*)x, (const float4*)W_in,
        (uint2*)W1, (uint2*)W2, (uint2*)xh, (uint2*)xl, (uint2*)Winh, (uint2*)Winl);

    // Launch 1: ext = x @ W_in^T + b_in; also writes s0 = ext[0] fp16
    {
        dim3 grid((BB * TT) / 64, SS / 64);
        proj_mma<<<grid, 256, P_SM>>>(xh, xl, Winh, Winl, b_in, ext, sA);
    }

    // Launches 2..513: scan, PDL-chained, 64-CTA grids, 2 CTAs/SM
    {
        cudaLaunchConfig_t cfg = {};
        cfg.gridDim  = dim3(BB / M_TILE, SS / N_TILE, 1);   // (4, 16) = 64 CTAs
        cfg.blockDim = dim3(NTHR, 1, 1);
        cfg.dynamicSmemBytes = SM_TOTAL;
        cudaLaunchAttribute at[1];
        at[0].id = cudaLaunchAttributeProgrammaticStreamSerialization;
        at[0].val.programmaticStreamSerializationAllowed = 1;
        cfg.attrs = at;
        cfg.numAttrs = 1;

        const float* nil = nullptr;
        for (int t = 0; t < TT; t++) {
            if (cudaLaunchKernelEx(&cfg, layer_kernel,
                    (const __half*)sA, (const __half*)W1,
                    (const float*)b_rec, nil, sB) != cudaSuccess)
                layer_kernel<<<cfg.gridDim, cfg.blockDim, SM_TOTAL>>>(
                    sA, W1, b_rec, nullptr, sB);
            const float* en = (t + 1 < TT) ? ext + (size_t)(t + 1) * BB * SS : nullptr;
            if (cudaLaunchKernelEx(&cfg, layer_kernel,
                    (const __half*)sB, (const __half*)W2,
                    (const float*)b_rec2, en, sA) != cudaSuccess)
                layer_kernel<<<cfg.gridDim, cfg.blockDim, SM_TOTAL>>>(
                    sB, W2, b_rec2, en, sA);
        }
    }

    // Final: broadcast final state
    bcastH_kernel<<<(BB * TT * SS / 4) / 256, 256>>>((const uint2*)sA, (float4*)out);
}

// round 15
// speedup vs baseline: 1.6581x; 1.6581x over previous
#include <cuda_runtime.h>
#include <cuda_bf16.h>
#include <cuda_fp16.h>
#include <cstdint>

// Problem dims
#define BB  256
#define TT  256
#define IND 128
#define SS  1024

// ---------------- scratch (__device__ globals) ------------------------------
__device__ float g_ext[(size_t)TT * BB * SS];            // [t][b][s] fp32
__device__ __half g_sA[BB * SS];                         // state fp16 (ping)
__device__ __half g_sB[BB * SS];                         // state fp16 (pong)
__device__ __half g_W1[SS * SS], g_W2[SS * SS];          // weights fp16
__device__ __nv_bfloat16 g_xh[(size_t)BB * TT * IND], g_xl[(size_t)BB * TT * IND];
__device__ __nv_bfloat16 g_Winh[SS * IND], g_Winl[SS * IND];

// ---------------- helpers ---------------------------------------------------
__device__ __forceinline__ uint32_t smem_u32(const void* p) {
    uint32_t a;
    asm("{ .reg .u64 t; cvta.to.shared.u64 t, %1; cvt.u32.u64 %0, t; }" : "=r"(a) : "l"(p));
    return a;
}
__device__ __forceinline__ void cp16(uint32_t dst, const void* src) {
    asm volatile("cp.async.cg.shared.global [%0], [%1], 16;" :: "r"(dst), "l"(src));
}
__device__ __forceinline__ void cp_commit() { asm volatile("cp.async.commit_group;"); }
__device__ __forceinline__ void cp_wait0()  { asm volatile("cp.async.wait_group 0;"); }
__device__ __forceinline__ void cp_wait1()  { asm volatile("cp.async.wait_group 1;"); }
__device__ __forceinline__ void gdc_wait()   { asm volatile("griddepcontrol.wait;" ::: "memory"); }
__device__ __forceinline__ void gdc_launch() { asm volatile("griddepcontrol.launch_dependents;"); }
__device__ __forceinline__ void bar_named256(int id) {
    asm volatile("bar.sync %0, 256;" :: "r"(id) : "memory");
}

__device__ __forceinline__ void mma_bf16(float* c, const uint32_t* a,
                                         uint32_t b0, uint32_t b1) {
    asm volatile(
        "mma.sync.aligned.m16n8k16.row.col.f32.bf16.bf16.f32 "
        "{%0,%1,%2,%3}, {%4,%5,%6,%7}, {%8,%9}, {%0,%1,%2,%3};"
        : "+f"(c[0]), "+f"(c[1]), "+f"(c[2]), "+f"(c[3])
        : "r"(a[0]), "r"(a[1]), "r"(a[2]), "r"(a[3]), "r"(b0), "r"(b1));
}
__device__ __forceinline__ void mma_f16(float* c, const uint32_t* a,
                                        uint32_t b0, uint32_t b1) {
    asm volatile(
        "mma.sync.aligned.m16n8k16.row.col.f32.f16.f16.f32 "
        "{%0,%1,%2,%3}, {%4,%5,%6,%7}, {%8,%9}, {%0,%1,%2,%3};"
        : "+f"(c[0]), "+f"(c[1]), "+f"(c[2]), "+f"(c[3])
        : "r"(a[0]), "r"(a[1]), "r"(a[2]), "r"(a[3]), "r"(b0), "r"(b1));
}
__device__ __forceinline__ void ldsm_x4(uint32_t* r, uint32_t addr) {
    asm volatile("ldmatrix.sync.aligned.m8n8.x4.shared.b16 {%0,%1,%2,%3}, [%4];"
                 : "=r"(r[0]), "=r"(r[1]), "=r"(r[2]), "=r"(r[3]) : "r"(addr));
}

// ---------------- layer GEMM (fp16, 2 groups x 3 stages, 2 CTAs/SM, PDL) ----
// O = relu(A @ W^T + bias) (+ ext_next). CTA tile 32x64, grid (8,16)=128 CTAs.
// 16 warps = 2 K-groups x (wm2 x wn4); group q (256 thr) owns k in
// [q*512, q*512+512), 8 chunks of 64 through a PRIVATE 3-stage pipeline
// (one 256-thread named bar per chunk, prefetch distance 2).
// SMEM 80KB -> 2 CTAs/SM: next layer's CTAs pre-place + prefetch W + ext
// BEFORE griddepcontrol.wait. 2-way cross-group reduction in epilogue.
#define M_TILE 32
#define N_TILE 64
#define KQ     512                // k-range per group
#define KCH    64                 // chunk width
#define NCH    8                  // chunks per group
#define STG_B  4096               // B offset inside a stage (A is 32*128)
#define STGSZ  12288              // stage: A 4KB + B 8KB
#define GREG   (3 * STGSZ)        // per-group region (3 stages) = 36864
#define EXT_OFF (2 * GREG)        // 73728
#define SM_TOTAL (EXT_OFF + 8192) // 81920 -> 2 CTAs/SM
#define NTHR   512

__device__ __forceinline__ void load_A(uint32_t dst, int k0, int gtid, int m0,
    const __half* __restrict__ A)
{
    // 32 rows x 8 units = 256 cp16, one per group thread
    int row = gtid >> 3, cu = gtid & 7;
    cp16(dst + row * 128 + ((cu ^ (row & 7)) << 4),
         A + (size_t)(m0 + row) * SS + k0 + cu * 8);
}
__device__ __forceinline__ void load_B(uint32_t dst, int k0, int gtid, int n0,
    const __half* __restrict__ W)
{
    // 64 rows x 8 units = 512 cp16, two per group thread
    #pragma unroll
    for (int i = 0; i < 2; i++) {
        int u = gtid + (i << 8);
        int row = u >> 3, cu = u & 7;
        cp16(dst + row * 128 + ((cu ^ (row & 7)) << 4),
             W + (size_t)(n0 + row) * SS + k0 + cu * 8);
    }
}

__global__ __launch_bounds__(NTHR, 2) void layer_kernel(
    const __half* __restrict__ A, const __half* __restrict__ W,
    const float* __restrict__ bias, const float* __restrict__ ext_next,
    __half* __restrict__ O)
{
    extern __shared__ char smem[];
    const uint32_t sb = smem_u32(smem);
    const int tid = threadIdx.x;
    const int wid = tid >> 5, lane = tid & 31;
    const int g = lane >> 2, t4 = lane & 3;
    const int q  = wid >> 3;             // K group 0..1
    const int wr = wid & 7;
    const int wm = (wr >> 2) & 1;        // rows wm*16
    const int wn = wr & 3;               // cols wn*16
    const int gtid = tid & 255;
    const int m0 = blockIdx.x * M_TILE, n0 = blockIdx.y * N_TILE;
    const int kbase = q * KQ;
    const uint32_t gb = sb + q * GREG;

    const int rowA = wm * 16 + (lane & 15);
    const int rowB = wn * 16 + (lane & 15);
    const int swA = rowA & 7, swB = rowB & 7;
    const int khalf = (lane >> 4) & 1;

    // ---- prologue: weight + ext prefetch BEFORE the grid dependency ----
    // (runs co-resident with the PREVIOUS layer thanks to 2 CTAs/SM)
    load_B(gb + STG_B, kbase, gtid, n0, W);
    if (ext_next) {                       // ext tile 32x64 fp32 = 8KB
        int row = tid >> 4, cu = tid & 15;
        cp16(sb + EXT_OFF + row * 256 + cu * 16,
             ext_next + (size_t)(m0 + row) * SS + n0 + cu * 4);
    }
    cp_commit();                                            // g0 = B0 (+ext)
    load_B(gb + STGSZ + STG_B, kbase + KCH, gtid, n0, W);
    cp_commit();                                            // g1 = B1
    gdc_wait();                                             // prev layer done
    load_A(gb, kbase, gtid, m0, A);              cp_commit(); // g2 = A0
    load_A(gb + STGSZ, kbase + KCH, gtid, m0, A); cp_commit(); // g3 = A1

    float acc[2][4] = {};

    // ---- group-private mainloop: 8 chunks, 3 stages, 1 bar/chunk ----
    int st_c = 0, st_p = 2;
    #pragma unroll 1
    for (int c = 0; c < NCH; c++) {
        if (c == NCH - 1) cp_wait0(); else cp_wait1();
        bar_named256(q + 1);              // chunk-c data complete, group-wide
        if (c + 2 < NCH) {
            const uint32_t sp = gb + st_p * STGSZ;  // holds chunk c-1: done
            load_A(sp, kbase + (c + 2) * KCH, gtid, m0, A);
            load_B(sp + STG_B, kbase + (c + 2) * KCH, gtid, n0, W);
            cp_commit();
        }
        const uint32_t aB = gb + st_c * STGSZ;
        const uint32_t bB = aB + STG_B;
        #pragma unroll
        for (int s = 0; s < 4; s++) {
            const int u = s * 2 + khalf;  // 0..7
            uint32_t a[4], b[4];
            ldsm_x4(a, aB + rowA * 128 + ((u ^ swA) << 4));
            ldsm_x4(b, bB + rowB * 128 + ((u ^ swB) << 4));
            mma_f16(acc[0], a, b[0], b[2]);
            mma_f16(acc[1], a, b[1], b[3]);
        }
        st_c = (st_c == 2) ? 0 : st_c + 1;
        st_p = (st_p == 2) ? 0 : st_p + 1;
    }

    gdc_launch();                         // successors place + prefetch
    __syncthreads();                      // all groups done -> overlay stages

    // ---- 2-way cross-group reduction (scratch overlays stage region) ----
    float* scr = (float*)smem;            // 8KB
    if (q == 1) {
        float4* p = (float4*)scr + (wr * 32 + lane) * 2;
        p[0] = make_float4(acc[0][0], acc[0][1], acc[0][2], acc[0][3]);
        p[1] = make_float4(acc[1][0], acc[1][1], acc[1][2], acc[1][3]);
    }
    __syncthreads();
    if (q == 0) {
        const float4* p = (const float4*)scr + (wr * 32 + lane) * 2;
        float4 v0 = p[0], v1 = p[1];
        acc[0][0] += v0.x; acc[0][1] += v0.y; acc[0][2] += v0.z; acc[0][3] += v0.w;
        acc[1][0] += v1.x; acc[1][1] += v1.y; acc[1][2] += v1.z; acc[1][3] += v1.w;

        // ---- epilogue: 8 warps cover the 32x64 tile ----
        const int row0 = m0 + wm * 16 + g;
        const int row1 = row0 + 8;
        #pragma unroll
        for (int j = 0; j < 2; j++) {
            const int col = n0 + wn * 16 + j * 8 + t4 * 2;
            float2 bb = *(const float2*)(bias + col);
            float v00 = fmaxf(acc[j][0] + bb.x, 0.0f);
            float v01 = fmaxf(acc[j][1] + bb.y, 0.0f);
            float v10 = fmaxf(acc[j][2] + bb.x, 0.0f);
            float v11 = fmaxf(acc[j][3] + bb.y, 0.0f);
            if (ext_next) {
                const char* eb = smem + EXT_OFF;
                const int ecol = (wn * 16 + j * 8 + t4 * 2) * 4;
                float2 e0 = *(const float2*)(eb + (wm * 16 + g) * 256 + ecol);
                float2 e1 = *(const float2*)(eb + (wm * 16 + g + 8) * 256 + ecol);
                v00 += e0.x; v01 += e0.y; v10 += e1.x; v11 += e1.y;
            }
            *(uint32_t*)(O + (size_t)row0 * SS + col) =
                (uint32_t)__half_as_ushort(__float2half_rn(v00))
                | ((uint32_t)__half_as_ushort(__float2half_rn(v01)) << 16);
            *(uint32_t*)(O + (size_t)row1 * SS + col) =
                (uint32_t)__half_as_ushort(__float2half_rn(v10))
                | ((uint32_t)__half_as_ushort(__float2half_rn(v11)) << 16);
        }
    }
}

// ---------------- input projection (bf16 3-term MMA; also writes s0) --------
#define PA_HI 0
#define PA_LO 16384
#define PB_HI 32768
#define PB_LO 49152
#define P_SM  65536

#define SWU16(cu, row) ((((cu) & 8) | (((cu) & 7) ^ ((row) & 7))) << 4)

__global__ __launch_bounds__(256) void proj_mma(
    const __nv_bfloat16* __restrict__ Xh, const __nv_bfloat16* __restrict__ Xl,
    const __nv_bfloat16* __restrict__ Wh, const __nv_bfloat16* __restrict__ Wl,
    const float* __restrict__ bias, float* __restrict__ Out,
    __half* __restrict__ S0)
{
    extern __shared__ char smem[];
    const uint32_t sb = smem_u32(smem);
    const int tid = threadIdx.x;
    const int wid = tid >> 5, lane = tid & 31;
    const int g = lane >> 2, t4 = lane & 3;
    const int wm = (wid >> 1) << 4;
    const int wn = (wid & 1) << 5;
    const int m0 = blockIdx.x * 64, n0 = blockIdx.y * 64;

    #pragma unroll
    for (int i = 0; i < 16; i++) {
        int u = tid + (i << 8);
        const __nv_bfloat16* src;
        uint32_t dst;
        if (u < 2048) {
            int sel = u >> 10, v = u & 1023;
            int row = v >> 4, cu = v & 15;
            src = (sel ? Xl : Xh) + (size_t)(m0 + row) * IND + cu * 8;
            dst = sb + (sel ? PA_LO : PA_HI) + row * 256 + SWU16(cu, row);
        } else {
            int w = u - 2048;
            int sel = w >> 10, v = w & 1023;
            int row = v >> 4, cu = v & 15;
            src = (sel ? Wl : Wh) + (size_t)(n0 + row) * IND + cu * 8;
            dst = sb + (sel ? PB_LO : PB_HI) + row * 256 + SWU16(cu, row);
        }
        cp16(dst, src);
    }
    cp_commit();
    cp_wait0();
    __syncthreads();

    const int lr = lane & 7;
    const int half8 = (lane >> 3) & 1;
    const int khalf = (lane >> 4) & 1;
    const int rowA = wm + half8 * 8 + lr;
    const int rowB = wn + half8 * 8 + lr;

    float acc[4][4] = {};
    #pragma unroll
    for (int ks = 0; ks < 8; ks++) {
        const int u = ks * 2 + khalf;
        uint32_t ah[4], al[4];
        ldsm_x4(ah, sb + PA_HI + rowA * 256 + SWU16(u, rowA));
        ldsm_x4(al, sb + PA_LO + rowA * 256 + SWU16(u, rowA));
        #pragma unroll
        for (int jj = 0; jj < 2; jj++) {
            uint32_t bh[4], bl[4];
            ldsm_x4(bh, sb + PB_HI + (rowB + jj * 16) * 256 + SWU16(u, rowB + jj * 16));
            ldsm_x4(bl, sb + PB_LO + (rowB + jj * 16) * 256 + SWU16(u, rowB + jj * 16));
            mma_bf16(acc[jj * 2],     ah, bh[0], bh[2]);
            mma_bf16(acc[jj * 2],     ah, bl[0], bl[2]);
            mma_bf16(acc[jj * 2],     al, bh[0], bh[2]);
            mma_bf16(acc[jj * 2 + 1], ah, bh[1], bh[3]);
            mma_bf16(acc[jj * 2 + 1], ah, bl[1], bl[3]);
            mma_bf16(acc[jj * 2 + 1], al, bh[1], bh[3]);
        }
    }

    const int r0 = m0 + wm + g;
    const int r1 = r0 + 8;
    const int b0r = r0 >> 8, t0r = r0 & 255;
    const int b1r = r1 >> 8, t1r = r1 & 255;
    #pragma unroll
    for (int j = 0; j < 4; j++) {
        const int col = n0 + wn + j * 8 + t4 * 2;
        float2 bb = *(const float2*)(bias + col);
        float2 o0 = make_float2(acc[j][0] + bb.x, acc[j][1] + bb.y);
        float2 o1 = make_float2(acc[j][2] + bb.x, acc[j][3] + bb.y);
        *(float2*)(Out + ((size_t)t0r * BB + b0r) * SS + col) = o0;
        *(float2*)(Out + ((size_t)t1r * BB + b1r) * SS + col) = o1;
        if (t0r == 0) {
            *(uint32_t*)(S0 + (size_t)b0r * SS + col) =
                (uint32_t)__half_as_ushort(__float2half_rn(o0.x))
                | ((uint32_t)__half_as_ushort(__float2half_rn(o0.y)) << 16);
        }
    }
}

// ---------------- fused prolog: all conversions in ONE launch ----------------
#define N_W   (SS * SS / 4)
#define N_X   ((size_t)BB * TT * IND / 4)
#define N_WIN (SS * IND / 4)
#define N_TOT (2 * N_W + (int)N_X + N_WIN)

__global__ void prep_kernel(
    const float4* __restrict__ Wr1, const float4* __restrict__ Wr2,
    const float4* __restrict__ X,   const float4* __restrict__ Win,
    uint2* __restrict__ W1, uint2* __restrict__ W2,
    uint2* __restrict__ xh, uint2* __restrict__ xl,
    uint2* __restrict__ wih, uint2* __restrict__ wil)
{
    int i = blockIdx.x * blockDim.x + threadIdx.x;
    if (i >= N_TOT) return;
    if (i < 2 * N_W) {
        const float4* src = (i < N_W) ? Wr1 : Wr2;
        uint2* dst        = (i < N_W) ? W1  : W2;
        int k = (i < N_W) ? i : i - N_W;
        float4 v = src[k];
        uint2 O;
        O.x = (uint32_t)__half_as_ushort(__float2half_rn(v.x))
            | ((uint32_t)__half_as_ushort(__float2half_rn(v.y)) << 16);
        O.y = (uint32_t)__half_as_ushort(__float2half_rn(v.z))
            | ((uint32_t)__half_as_ushort(__float2half_rn(v.w)) << 16);
        dst[k] = O;
    } else {
        int k = i - 2 * N_W;
        const float4* src; uint2 *dh, *dl;
        if (k < (int)N_X) { src = X; dh = xh; dl = xl; }
        else { k -= (int)N_X; src = Win; dh = wih; dl = wil; }
        float4 v = src[k];
        __nv_bfloat16 h0 = __float2bfloat16(v.x), h1 = __float2bfloat16(v.y);
        __nv_bfloat16 h2 = __float2bfloat16(v.z), h3 = __float2bfloat16(v.w);
        __nv_bfloat16 l0 = __float2bfloat16(v.x - __bfloat162float(h0));
        __nv_bfloat16 l1 = __float2bfloat16(v.y - __bfloat162float(h1));
        __nv_bfloat16 l2 = __float2bfloat16(v.z - __bfloat162float(h2));
        __nv_bfloat16 l3 = __float2bfloat16(v.w - __bfloat162float(h3));
        uint2 H, L;
        H.x = (uint32_t)__bfloat16_as_ushort(h0) | ((uint32_t)__bfloat16_as_ushort(h1) << 16);
        H.y = (uint32_t)__bfloat16_as_ushort(h2) | ((uint32_t)__bfloat16_as_ushort(h3) << 16);
        L.x = (uint32_t)__bfloat16_as_ushort(l0) | ((uint32_t)__bfloat16_as_ushort(l1) << 16);
        L.y = (uint32_t)__bfloat16_as_ushort(l2) | ((uint32_t)__bfloat16_as_ushort(l3) << 16);
        dh[k] = H; dl[k] = L;
    }
}

// ---------------- broadcast final state (fp16 -> fp32, all timesteps) -------
__global__ void bcastH_kernel(const uint2* __restrict__ s, float4* __restrict__ out)
{
    int i = blockIdx.x * blockDim.x + threadIdx.x;
    int b  = i >> 16;
    int s4 = i & 255;
    uint2 H = s[(b << 8) + s4];
    float4 o;
    o.x = __half2float(__ushort_as_half((unsigned short)(H.x & 0xFFFF)));
    o.y = __half2float(__ushort_as_half((unsigned short)(H.x >> 16)));
    o.z = __half2float(__ushort_as_half((unsigned short)(H.y & 0xFFFF)));
    o.w = __half2float(__ushort_as_half((unsigned short)(H.y >> 16)));
    out[i] = o;
}

// ---------------- driver ----------------------------------------------------
extern "C" void kernel_launch(void* const* d_in, const int* in_sizes, int n_in,
                              void* d_out, int out_size)
{
    const float* x      = (const float*)d_in[0];
    const float* W_in   = (const float*)d_in[1];
    const float* b_in   = (const float*)d_in[2];
    const float* W_rec  = (const float*)d_in[3];
    const float* b_rec  = (const float*)d_in[4];
    const float* W_rec2 = (const float*)d_in[5];
    const float* b_rec2 = (const float*)d_in[6];
    float* out = (float*)d_out;

    float* ext;
    __half *sA, *sB, *W1, *W2;
    __nv_bfloat16 *xh, *xl, *Winh, *Winl;
    cudaGetSymbolAddress((void**)&ext, g_ext);
    cudaGetSymbolAddress((void**)&sA,  g_sA);
    cudaGetSymbolAddress((void**)&sB,  g_sB);
    cudaGetSymbolAddress((void**)&W1,  g_W1);
    cudaGetSymbolAddress((void**)&W2,  g_W2);
    cudaGetSymbolAddress((void**)&xh,  g_xh);
    cudaGetSymbolAddress((void**)&xl,  g_xl);
    cudaGetSymbolAddress((void**)&Winh, g_Winh);
    cudaGetSymbolAddress((void**)&Winl, g_Winl);

    cudaFuncSetAttribute(layer_kernel, cudaFuncAttributeMaxDynamicSharedMemorySize, SM_TOTAL);
    cudaFuncSetAttribute(proj_mma,     cudaFuncAttributeMaxDynamicSharedMemorySize, P_SM);

    // Launch 0: fused prolog
    prep_kernel<<<(N_TOT + 255) / 256, 256>>>(
        (const float4*)W_rec, (const float4*)W_rec2,
        (const float4*)x, (const float4*)W_in,
        (uint2*)W1, (uint2*)W2, (uint2*)xh, (uint2*)xl, (uint2*)Winh, (uint2*)Winl);

    // Launch 1: ext = x @ W_in^T + b_in; also writes s0 = ext[0] fp16
    {
        dim3 grid((BB * TT) / 64, SS / 64);
        proj_mma<<<grid, 256, P_SM>>>(xh, xl, Winh, Winl, b_in, ext, sA);
    }

    // Launches 2..513: scan, PDL-chained, 128-CTA grids, 2 CTAs/SM
    {
        cudaLaunchConfig_t cfg = {};
        cfg.gridDim  = dim3(BB / M_TILE, SS / N_TILE, 1);   // (8, 16) = 128 CTAs
        cfg.blockDim = dim3(NTHR, 1, 1);
        cfg.dynamicSmemBytes = SM_TOTAL;
        cudaLaunchAttribute at[1];
        at[0].id = cudaLaunchAttributeProgrammaticStreamSerialization;
        at[0].val.programmaticStreamSerializationAllowed = 1;
        cfg.attrs = at;
        cfg.numAttrs = 1;

        const float* nil = nullptr;
        for (int t = 0; t < TT; t++) {
            if (cudaLaunchKernelEx(&cfg, layer_kernel,
                    (const __half*)sA, (const __half*)W1,
                    (const float*)b_rec, nil, sB) != cudaSuccess)
                layer_kernel<<<cfg.gridDim, cfg.blockDim, SM_TOTAL>>>(
                    sA, W1, b_rec, nullptr, sB);
            const float* en = (t + 1 < TT) ? ext + (size_t)(t + 1) * BB * SS : nullptr;
            if (cudaLaunchKernelEx(&cfg, layer_kernel,
                    (const __half*)sB, (const __half*)W2,
                    (const float*)b_rec2, en, sA) != cudaSuccess)
                layer_kernel<<<cfg.gridDim, cfg.blockDim, SM_TOTAL>>>(
                    sB, W2, b_rec2, en, sA);
        }
    }

    // Final: broadcast final state
    bcastH_kernel<<<(BB * TT * SS / 4) / 256, 256>>>((const uint2*)sA, (float4*)out);
}

// round 16
// speedup vs baseline: 2.3339x; 1.4076x over previous
#include <cuda_runtime.h>
#include <cuda_bf16.h>
#include <cuda_fp16.h>
#include <cstdint>

// Problem dims
#define BB  256
#define TT  256
#define IND 128
#define SS  1024

// ---------------- scratch (__device__ globals) ------------------------------
__device__ float g_ext[(size_t)TT * BB * SS];            // [t][b][s] fp32
__device__ __half g_sA[BB * SS];                         // state fp16 (ping)
__device__ __half g_sB[BB * SS];                         // state fp16 (pong)
__device__ __half g_W1[SS * SS], g_W2[SS * SS];          // weights fp16
__device__ __nv_bfloat16 g_xh[(size_t)BB * TT * IND], g_xl[(size_t)BB * TT * IND];
__device__ __nv_bfloat16 g_Winh[SS * IND], g_Winl[SS * IND];

// ---------------- helpers ---------------------------------------------------
__device__ __forceinline__ uint32_t smem_u32(const void* p) {
    uint32_t a;
    asm("{ .reg .u64 t; cvta.to.shared.u64 t, %1; cvt.u32.u64 %0, t; }" : "=r"(a) : "l"(p));
    return a;
}
__device__ __forceinline__ void cp16(uint32_t dst, const void* src) {
    asm volatile("cp.async.cg.shared.global [%0], [%1], 16;" :: "r"(dst), "l"(src));
}
__device__ __forceinline__ void cp_commit() { asm volatile("cp.async.commit_group;"); }
__device__ __forceinline__ void cp_wait0()  { asm volatile("cp.async.wait_group 0;"); }
__device__ __forceinline__ void cp_wait1()  { asm volatile("cp.async.wait_group 1;"); }
__device__ __forceinline__ void gdc_wait()   { asm volatile("griddepcontrol.wait;" ::: "memory"); }
__device__ __forceinline__ void gdc_launch() { asm volatile("griddepcontrol.launch_dependents;"); }
__device__ __forceinline__ void bar_named(int id) {
    asm volatile("bar.sync %0, 128;" :: "r"(id) : "memory");
}

__device__ __forceinline__ void mma_bf16(float* c, const uint32_t* a,
                                         uint32_t b0, uint32_t b1) {
    asm volatile(
        "mma.sync.aligned.m16n8k16.row.col.f32.bf16.bf16.f32 "
        "{%0,%1,%2,%3}, {%4,%5,%6,%7}, {%8,%9}, {%0,%1,%2,%3};"
        : "+f"(c[0]), "+f"(c[1]), "+f"(c[2]), "+f"(c[3])
        : "r"(a[0]), "r"(a[1]), "r"(a[2]), "r"(a[3]), "r"(b0), "r"(b1));
}
__device__ __forceinline__ void mma_f16(float* c, const uint32_t* a,
                                        uint32_t b0, uint32_t b1) {
    asm volatile(
        "mma.sync.aligned.m16n8k16.row.col.f32.f16.f16.f32 "
        "{%0,%1,%2,%3}, {%4,%5,%6,%7}, {%8,%9}, {%0,%1,%2,%3};"
        : "+f"(c[0]), "+f"(c[1]), "+f"(c[2]), "+f"(c[3])
        : "r"(a[0]), "r"(a[1]), "r"(a[2]), "r"(a[3]), "r"(b0), "r"(b1));
}
__device__ __forceinline__ void ldsm_x4(uint32_t* r, uint32_t addr) {
    asm volatile("ldmatrix.sync.aligned.m8n8.x4.shared.b16 {%0,%1,%2,%3}, [%4];"
                 : "=r"(r[0]), "=r"(r[1]), "=r"(r[2]), "=r"(r[3]) : "r"(addr));
}

// ---------------- layer GEMM: R11 config + SMEM-ext + early gdc_launch ------
// O = relu(A @ W^T + bias) (+ ext_next). CTA tile 32x64, grid (8,16)=128 CTAs.
// 16 warps = 4 K-groups x (wm2 x wn2); group q owns k in [q*256, q*256+256),
// 4 chunks of 64 through a PRIVATE 3-stage pipeline (128-wide named bars,
// prefetch distance 2, one bar per chunk). Symmetric 4-way reduction via a
// dedicated scratch region; kslot==0 warps store.
// NEW vs R11: ext tile prefetched into SMEM BEFORE griddepcontrol.wait, and
// gdc_launch fires right after the mainloop.
#define M_TILE 32
#define N_TILE 64
#define KQ     256                // k-range per group
#define KCH    64                 // chunk width
#define NCH    4                  // chunks per group
#define GSTG   12288              // per-group stage: A 4KB + B 8KB
#define STG_B  4096
#define STAGES 3
#define SCR_OFF (STAGES * 4 * GSTG)        // 147456
#define EXT_OFF (SCR_OFF + 32768)          // 180224
#define SM_TOTAL (EXT_OFF + 8192)          // 188416 + 8192 = 196608? no: 188416
#undef  SM_TOTAL
#define SM_TOTAL (EXT_OFF + 8192)          // 188416... EXT_OFF=180224 -> 188416
#define NTHR   512

__device__ __forceinline__ void load_A(uint32_t dst, int k0, int gtid, int m0,
    const __half* __restrict__ A)
{
    #pragma unroll
    for (int i = 0; i < 2; i++) {
        int u = gtid + (i << 7);         // 0..255 = 32 rows x 8 units
        int row = u >> 3, cu = u & 7;
        const __half* src = A + (size_t)(m0 + row) * SS + k0 + cu * 8;
        cp16(dst + row * 128 + ((cu ^ (row & 7)) << 4), src);
    }
}
__device__ __forceinline__ void load_B(uint32_t dst, int k0, int gtid, int n0,
    const __half* __restrict__ W)
{
    #pragma unroll
    for (int i = 0; i < 4; i++) {
        int u = gtid + (i << 7);         // 0..511 = 64 rows x 8 units
        int row = u >> 3, cu = u & 7;
        const __half* src = W + (size_t)(n0 + row) * SS + k0 + cu * 8;
        cp16(dst + row * 128 + ((cu ^ (row & 7)) << 4), src);
    }
}

__global__ __launch_bounds__(NTHR) void layer_kernel(
    const __half* __restrict__ A, const __half* __restrict__ W,
    const float* __restrict__ bias, const float* __restrict__ ext_next,
    __half* __restrict__ O)
{
    extern __shared__ char smem[];
    const uint32_t sb = smem_u32(smem);
    const int tid = threadIdx.x;
    const int wid = tid >> 5, lane = tid & 31;
    const int g = lane >> 2, t4 = lane & 3;
    const int q  = wid >> 2;             // K group 0..3
    const int wm = (wid >> 1) & 1;       // rows wm*16
    const int wn = wid & 1;              // cols wn*32
    const int gtid = tid & 127;
    const int m0 = blockIdx.x * M_TILE, n0 = blockIdx.y * N_TILE;
    const int kbase = q * KQ;
    const uint32_t gb = sb + q * (STAGES * GSTG);

    const int lr = lane & 7;
    const int half8 = (lane >> 3) & 1;
    const int khalf = (lane >> 4) & 1;
    const int rowA  = wm * 16 + half8 * 8 + lr;
    const int rowB0 = wn * 32 + half8 * 8 + lr;
    const int rowB1 = rowB0 + 16;
    const int swA = rowA & 7, swB0 = rowB0 & 7, swB1 = rowB1 & 7;

    // ---- prologue: weight + ext prefetch BEFORE the grid dependency ----
    load_B(gb + STG_B, kbase, gtid, n0, W);
    if (ext_next) {                       // ext tile 32x64 fp32 = 8KB, 512 thr
        int row = tid >> 4, cu = tid & 15;
        cp16(sb + EXT_OFF + row * 256 + cu * 16,
             ext_next + (size_t)(m0 + row) * SS + n0 + cu * 4);
    }
    cp_commit();                                            // g0 = B0 (+ext)
    load_B(gb + GSTG + STG_B, kbase + KCH, gtid, n0, W);
    cp_commit();                                            // g1 = B1
    gdc_wait();                                             // prev layer done
    load_A(gb, kbase, gtid, m0, A);            cp_commit(); // g2 = A0
    load_A(gb + GSTG, kbase + KCH, gtid, m0, A); cp_commit(); // g3 = A1

    float acc[4][4] = {};

    // ---- group-private mainloop: 4 chunks, 3 stages, named-bar sync ----
    #pragma unroll
    for (int c = 0; c < NCH; c++) {
        if (c == NCH - 1) cp_wait0(); else cp_wait1();
        bar_named(q + 1);                 // group data complete + stage reusable
        if (c + 2 < NCH) {
            const uint32_t sp = gb + ((c + 2) % 3) * GSTG;
            load_A(sp, kbase + (c + 2) * KCH, gtid, m0, A);
            load_B(sp + STG_B, kbase + (c + 2) * KCH, gtid, n0, W);
            cp_commit();
        }
        const uint32_t aB = gb + (c % 3) * GSTG;
        const uint32_t bB = aB + STG_B;
        #pragma unroll
        for (int s = 0; s < 4; s++) {
            const int u = s * 2 + khalf;  // 0..7
            uint32_t ah[4], b0[4], b1[4];
            ldsm_x4(ah, aB + rowA * 128 + ((u ^ swA) << 4));
            ldsm_x4(b0, bB + rowB0 * 128 + ((u ^ swB0) << 4));
            ldsm_x4(b1, bB + rowB1 * 128 + ((u ^ swB1) << 4));
            mma_f16(acc[0], ah, b0[0], b0[2]);
            mma_f16(acc[1], ah, b0[1], b0[3]);
            mma_f16(acc[2], ah, b1[0], b1[2]);
            mma_f16(acc[3], ah, b1[1], b1[3]);
        }
    }

    gdc_launch();                         // dependents may place + prefetch

    // ---- symmetric 4-way reduction: kslot!=0 warps dump, kslot==0 combine --
    const int tile = wm * 2 + wn;        // 0..3
    char* scr = smem + SCR_OFF;
    #pragma unroll
    for (int jj = 0; jj < 4; jj++) {
        if (jj != q) {
            float4* p = (float4*)(scr + (((tile * 4 + jj) * 4 + q) * 32 + lane) * 16);
            *p = make_float4(acc[jj][0], acc[jj][1], acc[jj][2], acc[jj][3]);
        }
    }
    __syncthreads();
    float r[4] = {acc[q][0], acc[q][1], acc[q][2], acc[q][3]};
    #pragma unroll
    for (int p = 0; p < 4; p++) {
        if (p != q) {
            float4 v = *(const float4*)(scr + (((tile * 4 + q) * 4 + p) * 32 + lane) * 16);
            r[0] += v.x; r[1] += v.y; r[2] += v.z; r[3] += v.w;
        }
    }

    // ---- epilogue: every warp handles its jj=q quadrant ----
    const int row0 = m0 + wm * 16 + g;
    const int row1 = row0 + 8;
    const int col  = n0 + wn * 32 + q * 8 + t4 * 2;
    float2 bb = *(const float2*)(bias + col);
    float v00 = fmaxf(r[0] + bb.x, 0.0f);
    float v01 = fmaxf(r[1] + bb.y, 0.0f);
    float v10 = fmaxf(r[2] + bb.x, 0.0f);
    float v11 = fmaxf(r[3] + bb.y, 0.0f);
    if (ext_next) {
        const char* eb = smem + EXT_OFF;
        const int ecol = (wn * 32 + q * 8 + t4 * 2) * 4;
        float2 e0 = *(const float2*)(eb + (wm * 16 + g) * 256 + ecol);
        float2 e1 = *(const float2*)(eb + (wm * 16 + g + 8) * 256 + ecol);
        v00 += e0.x; v01 += e0.y; v10 += e1.x; v11 += e1.y;
    }
    *(uint32_t*)(O + (size_t)row0 * SS + col) =
        (uint32_t)__half_as_ushort(__float2half_rn(v00))
        | ((uint32_t)__half_as_ushort(__float2half_rn(v01)) << 16);
    *(uint32_t*)(O + (size_t)row1 * SS + col) =
        (uint32_t)__half_as_ushort(__float2half_rn(v10))
        | ((uint32_t)__half_as_ushort(__float2half_rn(v11)) << 16);
}

// ---------------- input projection (bf16 3-term MMA; also writes s0) --------
#define PA_HI 0
#define PA_LO 16384
#define PB_HI 32768
#define PB_LO 49152
#define P_SM  65536

#define SWU16(cu, row) ((((cu) & 8) | (((cu) & 7) ^ ((row) & 7))) << 4)

__global__ __launch_bounds__(256) void proj_mma(
    const __nv_bfloat16* __restrict__ Xh, const __nv_bfloat16* __restrict__ Xl,
    const __nv_bfloat16* __restrict__ Wh, const __nv_bfloat16* __restrict__ Wl,
    const float* __restrict__ bias, float* __restrict__ Out,
    __half* __restrict__ S0)
{
    extern __shared__ char smem[];
    const uint32_t sb = smem_u32(smem);
    const int tid = threadIdx.x;
    const int wid = tid >> 5, lane = tid & 31;
    const int g = lane >> 2, t4 = lane & 3;
    const int wm = (wid >> 1) << 4;
    const int wn = (wid & 1) << 5;
    const int m0 = blockIdx.x * 64, n0 = blockIdx.y * 64;

    #pragma unroll
    for (int i = 0; i < 16; i++) {
        int u = tid + (i << 8);
        const __nv_bfloat16* src;
        uint32_t dst;
        if (u < 2048) {
            int sel = u >> 10, v = u & 1023;
            int row = v >> 4, cu = v & 15;
            src = (sel ? Xl : Xh) + (size_t)(m0 + row) * IND + cu * 8;
            dst = sb + (sel ? PA_LO : PA_HI) + row * 256 + SWU16(cu, row);
        } else {
            int w = u - 2048;
            int sel = w >> 10, v = w & 1023;
            int row = v >> 4, cu = v & 15;
            src = (sel ? Wl : Wh) + (size_t)(n0 + row) * IND + cu * 8;
            dst = sb + (sel ? PB_LO : PB_HI) + row * 256 + SWU16(cu, row);
        }
        cp16(dst, src);
    }
    cp_commit();
    cp_wait0();
    __syncthreads();

    const int lr = lane & 7;
    const int half8 = (lane >> 3) & 1;
    const int khalf = (lane >> 4) & 1;
    const int rowA = wm + half8 * 8 + lr;
    const int rowB = wn + half8 * 8 + lr;

    float acc[4][4] = {};
    #pragma unroll
    for (int ks = 0; ks < 8; ks++) {
        const int u = ks * 2 + khalf;
        uint32_t ah[4], al[4];
        ldsm_x4(ah, sb + PA_HI + rowA * 256 + SWU16(u, rowA));
        ldsm_x4(al, sb + PA_LO + rowA * 256 + SWU16(u, rowA));
        #pragma unroll
        for (int jj = 0; jj < 2; jj++) {
            uint32_t bh[4], bl[4];
            ldsm_x4(bh, sb + PB_HI + (rowB + jj * 16) * 256 + SWU16(u, rowB + jj * 16));
            ldsm_x4(bl, sb + PB_LO + (rowB + jj * 16) * 256 + SWU16(u, rowB + jj * 16));
            mma_bf16(acc[jj * 2],     ah, bh[0], bh[2]);
            mma_bf16(acc[jj * 2],     ah, bl[0], bl[2]);
            mma_bf16(acc[jj * 2],     al, bh[0], bh[2]);
            mma_bf16(acc[jj * 2 + 1], ah, bh[1], bh[3]);
            mma_bf16(acc[jj * 2 + 1], ah, bl[1], bl[3]);
            mma_bf16(acc[jj * 2 + 1], al, bh[1], bh[3]);
        }
    }

    const int r0 = m0 + wm + g;
    const int r1 = r0 + 8;
    const int b0r = r0 >> 8, t0r = r0 & 255;
    const int b1r = r1 >> 8, t1r = r1 & 255;
    #pragma unroll
    for (int j = 0; j < 4; j++) {
        const int col = n0 + wn + j * 8 + t4 * 2;
        float2 bb = *(const float2*)(bias + col);
        float2 o0 = make_float2(acc[j][0] + bb.x, acc[j][1] + bb.y);
        float2 o1 = make_float2(acc[j][2] + bb.x, acc[j][3] + bb.y);
        *(float2*)(Out + ((size_t)t0r * BB + b0r) * SS + col) = o0;
        *(float2*)(Out + ((size_t)t1r * BB + b1r) * SS + col) = o1;
        if (t0r == 0) {
            *(uint32_t*)(S0 + (size_t)b0r * SS + col) =
                (uint32_t)__half_as_ushort(__float2half_rn(o0.x))
                | ((uint32_t)__half_as_ushort(__float2half_rn(o0.y)) << 16);
        }
    }
}

// ---------------- fused prolog: all conversions in ONE launch ----------------
#define N_W   (SS * SS / 4)
#define N_X   ((size_t)BB * TT * IND / 4)
#define N_WIN (SS * IND / 4)
#define N_TOT (2 * N_W + (int)N_X + N_WIN)

__global__ void prep_kernel(
    const float4* __restrict__ Wr1, const float4* __restrict__ Wr2,
    const float4* __restrict__ X,   const float4* __restrict__ Win,
    uint2* __restrict__ W1, uint2* __restrict__ W2,
    uint2* __restrict__ xh, uint2* __restrict__ xl,
    uint2* __restrict__ wih, uint2* __restrict__ wil)
{
    int i = blockIdx.x * blockDim.x + threadIdx.x;
    if (i >= N_TOT) return;
    if (i < 2 * N_W) {
        const float4* src = (i < N_W) ? Wr1 : Wr2;
        uint2* dst        = (i < N_W) ? W1  : W2;
        int k = (i < N_W) ? i : i - N_W;
        float4 v = src[k];
        uint2 O;
        O.x = (uint32_t)__half_as_ushort(__float2half_rn(v.x))
            | ((uint32_t)__half_as_ushort(__float2half_rn(v.y)) << 16);
        O.y = (uint32_t)__half_as_ushort(__float2half_rn(v.z))
            | ((uint32_t)__half_as_ushort(__float2half_rn(v.w)) << 16);
        dst[k] = O;
    } else {
        int k = i - 2 * N_W;
        const float4* src; uint2 *dh, *dl;
        if (k < (int)N_X) { src = X; dh = xh; dl = xl; }
        else { k -= (int)N_X; src = Win; dh = wih; dl = wil; }
        float4 v = src[k];
        __nv_bfloat16 h0 = __float2bfloat16(v.x), h1 = __float2bfloat16(v.y);
        __nv_bfloat16 h2 = __float2bfloat16(v.z), h3 = __float2bfloat16(v.w);
        __nv_bfloat16 l0 = __float2bfloat16(v.x - __bfloat162float(h0));
        __nv_bfloat16 l1 = __float2bfloat16(v.y - __bfloat162float(h1));
        __nv_bfloat16 l2 = __float2bfloat16(v.z - __bfloat162float(h2));
        __nv_bfloat16 l3 = __float2bfloat16(v.w - __bfloat162float(h3));
        uint2 H, L;
        H.x = (uint32_t)__bfloat16_as_ushort(h0) | ((uint32_t)__bfloat16_as_ushort(h1) << 16);
        H.y = (uint32_t)__bfloat16_as_ushort(h2) | ((uint32_t)__bfloat16_as_ushort(h3) << 16);
        L.x = (uint32_t)__bfloat16_as_ushort(l0) | ((uint32_t)__bfloat16_as_ushort(l1) << 16);
        L.y = (uint32_t)__bfloat16_as_ushort(l2) | ((uint32_t)__bfloat16_as_ushort(l3) << 16);
        dh[k] = H; dl[k] = L;
    }
}

// ---------------- broadcast final state (fp16 -> fp32, all timesteps) -------
__global__ void bcastH_kernel(const uint2* __restrict__ s, float4* __restrict__ out)
{
    int i = blockIdx.x * blockDim.x + threadIdx.x;
    int b  = i >> 16;
    int s4 = i & 255;
    uint2 H = s[(b << 8) + s4];
    float4 o;
    o.x = __half2float(__ushort_as_half((unsigned short)(H.x & 0xFFFF)));
    o.y = __half2float(__ushort_as_half((unsigned short)(H.x >> 16)));
    o.z = __half2float(__ushort_as_half((unsigned short)(H.y & 0xFFFF)));
    o.w = __half2float(__ushort_as_half((unsigned short)(H.y >> 16)));
    out[i] = o;
}

// ---------------- driver ----------------------------------------------------
extern "C" void kernel_launch(void* const* d_in, const int* in_sizes, int n_in,
                              void* d_out, int out_size)
{
    const float* x      = (const float*)d_in[0];
    const float* W_in   = (const float*)d_in[1];
    const float* b_in   = (const float*)d_in[2];
    const float* W_rec  = (const float*)d_in[3];
    const float* b_rec  = (const float*)d_in[4];
    const float* W_rec2 = (const float*)d_in[5];
    const float* b_rec2 = (const float*)d_in[6];
    float* out = (float*)d_out;

    float* ext;
    __half *sA, *sB, *W1, *W2;
    __nv_bfloat16 *xh, *xl, *Winh, *Winl;
    cudaGetSymbolAddress((void**)&ext, g_ext);
    cudaGetSymbolAddress((void**)&sA,  g_sA);
    cudaGetSymbolAddress((void**)&sB,  g_sB);
    cudaGetSymbolAddress((void**)&W1,  g_W1);
    cudaGetSymbolAddress((void**)&W2,  g_W2);
    cudaGetSymbolAddress((void**)&xh,  g_xh);
    cudaGetSymbolAddress((void**)&xl,  g_xl);
    cudaGetSymbolAddress((void**)&Winh, g_Winh);
    cudaGetSymbolAddress((void**)&Winl, g_Winl);

    cudaFuncSetAttribute(layer_kernel, cudaFuncAttributeMaxDynamicSharedMemorySize, SM_TOTAL);
    cudaFuncSetAttribute(proj_mma,     cudaFuncAttributeMaxDynamicSharedMemorySize, P_SM);

    // Launch 0: fused prolog
    prep_kernel<<<(N_TOT + 255) / 256, 256>>>(
        (const float4*)W_rec, (const float4*)W_rec2,
        (const float4*)x, (const float4*)W_in,
        (uint2*)W1, (uint2*)W2, (uint2*)xh, (uint2*)xl, (uint2*)Winh, (uint2*)Winl);

    // Launch 1: ext = x @ W_in^T + b_in; also writes s0 = ext[0] fp16
    {
        dim3 grid((BB * TT) / 64, SS / 64);
        proj_mma<<<grid, 256, P_SM>>>(xh, xl, Winh, Winl, b_in, ext, sA);
    }

    // Launches 2..513: scan, PDL-chained (R11 config)
    {
        cudaLaunchConfig_t cfg = {};
        cfg.gridDim  = dim3(BB / M_TILE, SS / N_TILE, 1);   // (8, 16) = 128 CTAs
        cfg.blockDim = dim3(NTHR, 1, 1);
        cfg.dynamicSmemBytes = SM_TOTAL;
        cudaLaunchAttribute at[1];
        at[0].id = cudaLaunchAttributeProgrammaticStreamSerialization;
        at[0].val.programmaticStreamSerializationAllowed = 1;
        cfg.attrs = at;
        cfg.numAttrs = 1;

        const float* nil = nullptr;
        for (int t = 0; t < TT; t++) {
            if (cudaLaunchKernelEx(&cfg, layer_kernel,
                    (const __half*)sA, (const __half*)W1,
                    (const float*)b_rec, nil, sB) != cudaSuccess)
                layer_kernel<<<cfg.gridDim, cfg.blockDim, SM_TOTAL>>>(
                    sA, W1, b_rec, nullptr, sB);
            const float* en = (t + 1 < TT) ? ext + (size_t)(t + 1) * BB * SS : nullptr;
            if (cudaLaunchKernelEx(&cfg, layer_kernel,
                    (const __half*)sB, (const __half*)W2,
                    (const float*)b_rec2, en, sA) != cudaSuccess)
                layer_kernel<<<cfg.gridDim, cfg.blockDim, SM_TOTAL>>>(
                    sB, W2, b_rec2, en, sA);
        }
    }

    // Final: broadcast final state
    bcastH_kernel<<<(BB * TT * SS / 4) / 256, 256>>>((const uint2*)sA, (float4*)out);
}

// round 17
// speedup vs baseline: 2.3419x; 1.0034x over previous
#include <cuda_runtime.h>
#include <cuda_bf16.h>
#include <cuda_fp16.h>
#include <cstdint>

// Problem dims
#define BB  256
#define TT  256
#define IND 128
#define SS  1024

// ---------------- scratch (__device__ globals) ------------------------------
__device__ float g_ext[(size_t)TT * BB * SS];            // [t][b][s] fp32
__device__ __half g_sA[BB * SS];                         // state fp16 (ping)
__device__ __half g_sB[BB * SS];                         // state fp16 (pong)
__device__ __half g_W1[SS * SS], g_W2[SS * SS];          // weights fp16
__device__ __nv_bfloat16 g_xh[(size_t)BB * TT * IND], g_xl[(size_t)BB * TT * IND];
__device__ __nv_bfloat16 g_Winh[SS * IND], g_Winl[SS * IND];

// ---------------- helpers ---------------------------------------------------
__device__ __forceinline__ uint32_t smem_u32(const void* p) {
    uint32_t a;
    asm("{ .reg .u64 t; cvta.to.shared.u64 t, %1; cvt.u32.u64 %0, t; }" : "=r"(a) : "l"(p));
    return a;
}
__device__ __forceinline__ void cp16(uint32_t dst, const void* src) {
    asm volatile("cp.async.cg.shared.global [%0], [%1], 16;" :: "r"(dst), "l"(src));
}
__device__ __forceinline__ void cp_commit() { asm volatile("cp.async.commit_group;"); }
__device__ __forceinline__ void cp_wait0()  { asm volatile("cp.async.wait_group 0;"); }
__device__ __forceinline__ void cp_wait1()  { asm volatile("cp.async.wait_group 1;"); }
__device__ __forceinline__ void gdc_wait()   { asm volatile("griddepcontrol.wait;" ::: "memory"); }
__device__ __forceinline__ void gdc_launch() { asm volatile("griddepcontrol.launch_dependents;"); }
__device__ __forceinline__ void bar_named(int id) {
    asm volatile("bar.sync %0, 128;" :: "r"(id) : "memory");
}

__device__ __forceinline__ void mma_bf16(float* c, const uint32_t* a,
                                         uint32_t b0, uint32_t b1) {
    asm volatile(
        "mma.sync.aligned.m16n8k16.row.col.f32.bf16.bf16.f32 "
        "{%0,%1,%2,%3}, {%4,%5,%6,%7}, {%8,%9}, {%0,%1,%2,%3};"
        : "+f"(c[0]), "+f"(c[1]), "+f"(c[2]), "+f"(c[3])
        : "r"(a[0]), "r"(a[1]), "r"(a[2]), "r"(a[3]), "r"(b0), "r"(b1));
}
__device__ __forceinline__ void mma_f16(float* c, const uint32_t* a,
                                        uint32_t b0, uint32_t b1) {
    asm volatile(
        "mma.sync.aligned.m16n8k16.row.col.f32.f16.f16.f32 "
        "{%0,%1,%2,%3}, {%4,%5,%6,%7}, {%8,%9}, {%0,%1,%2,%3};"
        : "+f"(c[0]), "+f"(c[1]), "+f"(c[2]), "+f"(c[3])
        : "r"(a[0]), "r"(a[1]), "r"(a[2]), "r"(a[3]), "r"(b0), "r"(b1));
}
__device__ __forceinline__ void ldsm_x4(uint32_t* r, uint32_t addr) {
    asm volatile("ldmatrix.sync.aligned.m8n8.x4.shared.b16 {%0,%1,%2,%3}, [%4];"
                 : "=r"(r[0]), "=r"(r[1]), "=r"(r[2]), "=r"(r[3]) : "r"(addr));
}

// ---------------- layer GEMM: R16 config, B fully pre-wait prefetched -------
// O = relu(A @ W^T + bias) (+ ext_next). CTA tile 32x64, grid (8,16)=128 CTAs.
// 16 warps = 4 K-groups x (wm2 x wn2); group q owns k in [q*256, q*256+256),
// 4 chunks of 64. Per group: A has 3 rotating stages (4KB each), B has 4
// DIRECT stages (8KB each) -- ALL weight chunks + ext tile are prefetched
// BEFORE griddepcontrol.wait (weights/ext don't depend on the prev layer, and
// the loads overlap the previous grid's drain/straggler window).
// Post-wait: only A loads. One 128-wide named bar per chunk, uniform wait1.
// Symmetric 4-way reduction via dedicated scratch; early gdc_launch.
#define M_TILE 32
#define N_TILE 64
#define KQ     256                // k-range per group
#define KCH    64                 // chunk width
#define NCH    4                  // chunks per group
#define A_STG  4096               // A stage size (32x64 fp16)
#define B_STG  8192               // B stage size (64x64 fp16)
#define B_OFF  (3 * A_STG)        // B region offset inside group = 12288
#define GREG   (B_OFF + 4 * B_STG)        // 45056 per group
#define SCR_OFF (4 * GREG)                // 180224
#define EXT_OFF (SCR_OFF + 32768)         // 212992
#define SM_TOTAL (EXT_OFF + 8192)         // 221184
#define NTHR   512

__device__ __forceinline__ void load_A(uint32_t dst, int k0, int gtid, int m0,
    const __half* __restrict__ A)
{
    #pragma unroll
    for (int i = 0; i < 2; i++) {
        int u = gtid + (i << 7);         // 0..255 = 32 rows x 8 units
        int row = u >> 3, cu = u & 7;
        const __half* src = A + (size_t)(m0 + row) * SS + k0 + cu * 8;
        cp16(dst + row * 128 + ((cu ^ (row & 7)) << 4), src);
    }
}
__device__ __forceinline__ void load_B(uint32_t dst, int k0, int gtid, int n0,
    const __half* __restrict__ W)
{
    #pragma unroll
    for (int i = 0; i < 4; i++) {
        int u = gtid + (i << 7);         // 0..511 = 64 rows x 8 units
        int row = u >> 3, cu = u & 7;
        const __half* src = W + (size_t)(n0 + row) * SS + k0 + cu * 8;
        cp16(dst + row * 128 + ((cu ^ (row & 7)) << 4), src);
    }
}

__global__ __launch_bounds__(NTHR) void layer_kernel(
    const __half* __restrict__ A, const __half* __restrict__ W,
    const float* __restrict__ bias, const float* __restrict__ ext_next,
    __half* __restrict__ O)
{
    extern __shared__ char smem[];
    const uint32_t sb = smem_u32(smem);
    const int tid = threadIdx.x;
    const int wid = tid >> 5, lane = tid & 31;
    const int g = lane >> 2, t4 = lane & 3;
    const int q  = wid >> 2;             // K group 0..3
    const int wm = (wid >> 1) & 1;       // rows wm*16
    const int wn = wid & 1;              // cols wn*32
    const int gtid = tid & 127;
    const int m0 = blockIdx.x * M_TILE, n0 = blockIdx.y * N_TILE;
    const int kbase = q * KQ;
    const uint32_t gb = sb + q * GREG;

    const int lr = lane & 7;
    const int half8 = (lane >> 3) & 1;
    const int khalf = (lane >> 4) & 1;
    const int rowA  = wm * 16 + half8 * 8 + lr;
    const int rowB0 = wn * 32 + half8 * 8 + lr;
    const int rowB1 = rowB0 + 16;
    const int swA = rowA & 7, swB0 = rowB0 & 7, swB1 = rowB1 & 7;

    // ---- prologue: ALL weight chunks + ext BEFORE the grid dependency ----
    load_B(gb + B_OFF, kbase, gtid, n0, W);
    if (ext_next) {                       // ext tile 32x64 fp32 = 8KB, 512 thr
        int row = tid >> 4, cu = tid & 15;
        cp16(sb + EXT_OFF + row * 256 + cu * 16,
             ext_next + (size_t)(m0 + row) * SS + n0 + cu * 4);
    }
    cp_commit();                                              // g0 = B0 (+ext)
    load_B(gb + B_OFF + B_STG,     kbase + KCH,     gtid, n0, W); cp_commit(); // g1
    load_B(gb + B_OFF + 2 * B_STG, kbase + 2 * KCH, gtid, n0, W); cp_commit(); // g2
    load_B(gb + B_OFF + 3 * B_STG, kbase + 3 * KCH, gtid, n0, W); cp_commit(); // g3
    gdc_wait();                                               // prev layer done
    load_A(gb,         kbase,       gtid, m0, A); cp_commit(); // g4 = A0
    load_A(gb + A_STG, kbase + KCH, gtid, m0, A); cp_commit(); // g5 = A1

    float acc[4][4] = {};

    // ---- group-private mainloop: 4 chunks, A 3-stage rotate, B direct ----
    #pragma unroll
    for (int c = 0; c < NCH; c++) {
        if (c == NCH - 1) cp_wait0(); else cp_wait1();
        bar_named(q + 1);                 // chunk-c data complete, group-wide
        if (c + 2 < NCH) {                // A stage (c+2)%3 freed at this bar
            load_A(gb + ((c + 2) % 3) * A_STG, kbase + (c + 2) * KCH, gtid, m0, A);
            cp_commit();
        }
        const uint32_t aB = gb + (c % 3) * A_STG;
        const uint32_t bB = gb + B_OFF + c * B_STG;
        #pragma unroll
        for (int s = 0; s < 4; s++) {
            const int u = s * 2 + khalf;  // 0..7
            uint32_t ah[4], b0[4], b1[4];
            ldsm_x4(ah, aB + rowA * 128 + ((u ^ swA) << 4));
            ldsm_x4(b0, bB + rowB0 * 128 + ((u ^ swB0) << 4));
            ldsm_x4(b1, bB + rowB1 * 128 + ((u ^ swB1) << 4));
            mma_f16(acc[0], ah, b0[0], b0[2]);
            mma_f16(acc[1], ah, b0[1], b0[3]);
            mma_f16(acc[2], ah, b1[0], b1[2]);
            mma_f16(acc[3], ah, b1[1], b1[3]);
        }
    }

    gdc_launch();                         // dependents may place + prefetch

    // ---- symmetric 4-way reduction (dedicated scratch region) ----
    const int tile = wm * 2 + wn;        // 0..3
    char* scr = smem + SCR_OFF;
    #pragma unroll
    for (int jj = 0; jj < 4; jj++) {
        if (jj != q) {
            float4* p = (float4*)(scr + (((tile * 4 + jj) * 4 + q) * 32 + lane) * 16);
            *p = make_float4(acc[jj][0], acc[jj][1], acc[jj][2], acc[jj][3]);
        }
    }
    __syncthreads();
    float r[4] = {acc[q][0], acc[q][1], acc[q][2], acc[q][3]};
    #pragma unroll
    for (int p = 0; p < 4; p++) {
        if (p != q) {
            float4 v = *(const float4*)(scr + (((tile * 4 + q) * 4 + p) * 32 + lane) * 16);
            r[0] += v.x; r[1] += v.y; r[2] += v.z; r[3] += v.w;
        }
    }

    // ---- epilogue: every warp handles its jj=q quadrant ----
    const int row0 = m0 + wm * 16 + g;
    const int row1 = row0 + 8;
    const int col  = n0 + wn * 32 + q * 8 + t4 * 2;
    float2 bb = *(const float2*)(bias + col);
    float v00 = fmaxf(r[0] + bb.x, 0.0f);
    float v01 = fmaxf(r[1] + bb.y, 0.0f);
    float v10 = fmaxf(r[2] + bb.x, 0.0f);
    float v11 = fmaxf(r[3] + bb.y, 0.0f);
    if (ext_next) {
        const char* eb = smem + EXT_OFF;
        const int ecol = (wn * 32 + q * 8 + t4 * 2) * 4;
        float2 e0 = *(const float2*)(eb + (wm * 16 + g) * 256 + ecol);
        float2 e1 = *(const float2*)(eb + (wm * 16 + g + 8) * 256 + ecol);
        v00 += e0.x; v01 += e0.y; v10 += e1.x; v11 += e1.y;
    }
    *(uint32_t*)(O + (size_t)row0 * SS + col) =
        (uint32_t)__half_as_ushort(__float2half_rn(v00))
        | ((uint32_t)__half_as_ushort(__float2half_rn(v01)) << 16);
    *(uint32_t*)(O + (size_t)row1 * SS + col) =
        (uint32_t)__half_as_ushort(__float2half_rn(v10))
        | ((uint32_t)__half_as_ushort(__float2half_rn(v11)) << 16);
}

// ---------------- input projection (bf16 3-term MMA; also writes s0) --------
#define PA_HI 0
#define PA_LO 16384
#define PB_HI 32768
#define PB_LO 49152
#define P_SM  65536

#define SWU16(cu, row) ((((cu) & 8) | (((cu) & 7) ^ ((row) & 7))) << 4)

__global__ __launch_bounds__(256) void proj_mma(
    const __nv_bfloat16* __restrict__ Xh, const __nv_bfloat16* __restrict__ Xl,
    const __nv_bfloat16* __restrict__ Wh, const __nv_bfloat16* __restrict__ Wl,
    const float* __restrict__ bias, float* __restrict__ Out,
    __half* __restrict__ S0)
{
    extern __shared__ char smem[];
    const uint32_t sb = smem_u32(smem);
    const int tid = threadIdx.x;
    const int wid = tid >> 5, lane = tid & 31;
    const int g = lane >> 2, t4 = lane & 3;
    const int wm = (wid >> 1) << 4;
    const int wn = (wid & 1) << 5;
    const int m0 = blockIdx.x * 64, n0 = blockIdx.y * 64;

    #pragma unroll
    for (int i = 0; i < 16; i++) {
        int u = tid + (i << 8);
        const __nv_bfloat16* src;
        uint32_t dst;
        if (u < 2048) {
            int sel = u >> 10, v = u & 1023;
            int row = v >> 4, cu = v & 15;
            src = (sel ? Xl : Xh) + (size_t)(m0 + row) * IND + cu * 8;
            dst = sb + (sel ? PA_LO : PA_HI) + row * 256 + SWU16(cu, row);
        } else {
            int w = u - 2048;
            int sel = w >> 10, v = w & 1023;
            int row = v >> 4, cu = v & 15;
            src = (sel ? Wl : Wh) + (size_t)(n0 + row) * IND + cu * 8;
            dst = sb + (sel ? PB_LO : PB_HI) + row * 256 + SWU16(cu, row);
        }
        cp16(dst, src);
    }
    cp_commit();
    cp_wait0();
    __syncthreads();

    const int lr = lane & 7;
    const int half8 = (lane >> 3) & 1;
    const int khalf = (lane >> 4) & 1;
    const int rowA = wm + half8 * 8 + lr;
    const int rowB = wn + half8 * 8 + lr;

    float acc[4][4] = {};
    #pragma unroll
    for (int ks = 0; ks < 8; ks++) {
        const int u = ks * 2 + khalf;
        uint32_t ah[4], al[4];
        ldsm_x4(ah, sb + PA_HI + rowA * 256 + SWU16(u, rowA));
        ldsm_x4(al, sb + PA_LO + rowA * 256 + SWU16(u, rowA));
        #pragma unroll
        for (int jj = 0; jj < 2; jj++) {
            uint32_t bh[4], bl[4];
            ldsm_x4(bh, sb + PB_HI + (rowB + jj * 16) * 256 + SWU16(u, rowB + jj * 16));
            ldsm_x4(bl, sb + PB_LO + (rowB + jj * 16) * 256 + SWU16(u, rowB + jj * 16));
            mma_bf16(acc[jj * 2],     ah, bh[0], bh[2]);
            mma_bf16(acc[jj * 2],     ah, bl[0], bl[2]);
            mma_bf16(acc[jj * 2],     al, bh[0], bh[2]);
            mma_bf16(acc[jj * 2 + 1], ah, bh[1], bh[3]);
            mma_bf16(acc[jj * 2 + 1], ah, bl[1], bl[3]);
            mma_bf16(acc[jj * 2 + 1], al, bh[1], bh[3]);
        }
    }

    const int r0 = m0 + wm + g;
    const int r1 = r0 + 8;
    const int b0r = r0 >> 8, t0r = r0 & 255;
    const int b1r = r1 >> 8, t1r = r1 & 255;
    #pragma unroll
    for (int j = 0; j < 4; j++) {
        const int col = n0 + wn + j * 8 + t4 * 2;
        float2 bb = *(const float2*)(bias + col);
        float2 o0 = make_float2(acc[j][0] + bb.x, acc[j][1] + bb.y);
        float2 o1 = make_float2(acc[j][2] + bb.x, acc[j][3] + bb.y);
        *(float2*)(Out + ((size_t)t0r * BB + b0r) * SS + col) = o0;
        *(float2*)(Out + ((size_t)t1r * BB + b1r) * SS + col) = o1;
        if (t0r == 0) {
            *(uint32_t*)(S0 + (size_t)b0r * SS + col) =
                (uint32_t)__half_as_ushort(__float2half_rn(o0.x))
                | ((uint32_t)__half_as_ushort(__float2half_rn(o0.y)) << 16);
        }
    }
}

// ---------------- fused prolog: all conversions in ONE launch ----------------
#define N_W   (SS * SS / 4)
#define N_X   ((size_t)BB * TT * IND / 4)
#define N_WIN (SS * IND / 4)
#define N_TOT (2 * N_W + (int)N_X + N_WIN)

__global__ void prep_kernel(
    const float4* __restrict__ Wr1, const float4* __restrict__ Wr2,
    const float4* __restrict__ X,   const float4* __restrict__ Win,
    uint2* __restrict__ W1, uint2* __restrict__ W2,
    uint2* __restrict__ xh, uint2* __restrict__ xl,
    uint2* __restrict__ wih, uint2* __restrict__ wil)
{
    int i = blockIdx.x * blockDim.x + threadIdx.x;
    if (i >= N_TOT) return;
    if (i < 2 * N_W) {
        const float4* src = (i < N_W) ? Wr1 : Wr2;
        uint2* dst        = (i < N_W) ? W1  : W2;
        int k = (i < N_W) ? i : i - N_W;
        float4 v = src[k];
        uint2 O;
        O.x = (uint32_t)__half_as_ushort(__float2half_rn(v.x))
            | ((uint32_t)__half_as_ushort(__float2half_rn(v.y)) << 16);
        O.y = (uint32_t)__half_as_ushort(__float2half_rn(v.z))
            | ((uint32_t)__half_as_ushort(__float2half_rn(v.w)) << 16);
        dst[k] = O;
    } else {
        int k = i - 2 * N_W;
        const float4* src; uint2 *dh, *dl;
        if (k < (int)N_X) { src = X; dh = xh; dl = xl; }
        else { k -= (int)N_X; src = Win; dh = wih; dl = wil; }
        float4 v = src[k];
        __nv_bfloat16 h0 = __float2bfloat16(v.x), h1 = __float2bfloat16(v.y);
        __nv_bfloat16 h2 = __float2bfloat16(v.z), h3 = __float2bfloat16(v.w);
        __nv_bfloat16 l0 = __float2bfloat16(v.x - __bfloat162float(h0));
        __nv_bfloat16 l1 = __float2bfloat16(v.y - __bfloat162float(h1));
        __nv_bfloat16 l2 = __float2bfloat16(v.z - __bfloat162float(h2));
        __nv_bfloat16 l3 = __float2bfloat16(v.w - __bfloat162float(h3));
        uint2 H, L;
        H.x = (uint32_t)__bfloat16_as_ushort(h0) | ((uint32_t)__bfloat16_as_ushort(h1) << 16);
        H.y = (uint32_t)__bfloat16_as_ushort(h2) | ((uint32_t)__bfloat16_as_ushort(h3) << 16);
        L.x = (uint32_t)__bfloat16_as_ushort(l0) | ((uint32_t)__bfloat16_as_ushort(l1) << 16);
        L.y = (uint32_t)__bfloat16_as_ushort(l2) | ((uint32_t)__bfloat16_as_ushort(l3) << 16);
        dh[k] = H; dl[k] = L;
    }
}

// ---------------- broadcast final state (fp16 -> fp32, all timesteps) -------
__global__ void bcastH_kernel(const uint2* __restrict__ s, float4* __restrict__ out)
{
    int i = blockIdx.x * blockDim.x + threadIdx.x;
    int b  = i >> 16;
    int s4 = i & 255;
    uint2 H = s[(b << 8) + s4];
    float4 o;
    o.x = __half2float(__ushort_as_half((unsigned short)(H.x & 0xFFFF)));
    o.y = __half2float(__ushort_as_half((unsigned short)(H.x >> 16)));
    o.z = __half2float(__ushort_as_half((unsigned short)(H.y & 0xFFFF)));
    o.w = __half2float(__ushort_as_half((unsigned short)(H.y >> 16)));
    out[i] = o;
}

// ---------------- driver ----------------------------------------------------
extern "C" void kernel_launch(void* const* d_in, const int* in_sizes, int n_in,
                              void* d_out, int out_size)
{
    const float* x      = (const float*)d_in[0];
    const float* W_in   = (const float*)d_in[1];
    const float* b_in   = (const float*)d_in[2];
    const float* W_rec  = (const float*)d_in[3];
    const float* b_rec  = (const float*)d_in[4];
    const float* W_rec2 = (const float*)d_in[5];
    const float* b_rec2 = (const float*)d_in[6];
    float* out = (float*)d_out;

    float* ext;
    __half *sA, *sB, *W1, *W2;
    __nv_bfloat16 *xh, *xl, *Winh, *Winl;
    cudaGetSymbolAddress((void**)&ext, g_ext);
    cudaGetSymbolAddress((void**)&sA,  g_sA);
    cudaGetSymbolAddress((void**)&sB,  g_sB);
    cudaGetSymbolAddress((void**)&W1,  g_W1);
    cudaGetSymbolAddress((void**)&W2,  g_W2);
    cudaGetSymbolAddress((void**)&xh,  g_xh);
    cudaGetSymbolAddress((void**)&xl,  g_xl);
    cudaGetSymbolAddress((void**)&Winh, g_Winh);
    cudaGetSymbolAddress((void**)&Winl, g_Winl);

    cudaFuncSetAttribute(layer_kernel, cudaFuncAttributeMaxDynamicSharedMemorySize, SM_TOTAL);
    cudaFuncSetAttribute(proj_mma,     cudaFuncAttributeMaxDynamicSharedMemorySize, P_SM);

    // Launch 0: fused prolog
    prep_kernel<<<(N_TOT + 255) / 256, 256>>>(
        (const float4*)W_rec, (const float4*)W_rec2,
        (const float4*)x, (const float4*)W_in,
        (uint2*)W1, (uint2*)W2, (uint2*)xh, (uint2*)xl, (uint2*)Winh, (uint2*)Winl);

    // Launch 1: ext = x @ W_in^T + b_in; also writes s0 = ext[0] fp16
    {
        dim3 grid((BB * TT) / 64, SS / 64);
        proj_mma<<<grid, 256, P_SM>>>(xh, xl, Winh, Winl, b_in, ext, sA);
    }

    // Launches 2..513: scan, PDL-chained
    {
        cudaLaunchConfig_t cfg = {};
        cfg.gridDim  = dim3(BB / M_TILE, SS / N_TILE, 1);   // (8, 16) = 128 CTAs
        cfg.blockDim = dim3(NTHR, 1, 1);
        cfg.dynamicSmemBytes = SM_TOTAL;
        cudaLaunchAttribute at[1];
        at[0].id = cudaLaunchAttributeProgrammaticStreamSerialization;
        at[0].val.programmaticStreamSerializationAllowed = 1;
        cfg.attrs = at;
        cfg.numAttrs = 1;

        const float* nil = nullptr;
        for (int t = 0; t < TT; t++) {
            if (cudaLaunchKernelEx(&cfg, layer_kernel,
                    (const __half*)sA, (const __half*)W1,
                    (const float*)b_rec, nil, sB) != cudaSuccess)
                layer_kernel<<<cfg.gridDim, cfg.blockDim, SM_TOTAL>>>(
                    sA, W1, b_rec, nullptr, sB);
            const float* en = (t + 1 < TT) ? ext + (size_t)(t + 1) * BB * SS : nullptr;
            if (cudaLaunchKernelEx(&cfg, layer_kernel,
                    (const __half*)sB, (const __half*)W2,
                    (const float*)b_rec2, en, sA) != cudaSuccess)
                layer_kernel<<<cfg.gridDim, cfg.blockDim, SM_TOTAL>>>(
                    sB, W2, b_rec2, en, sA);
        }
    }

    // Final: broadcast final state
    bcastH_kernel<<<(BB * TT * SS / 4) / 256, 256>>>((const uint2*)sA, (float4*)out);
}